// round 11
// baseline (speedup 1.0000x reference)
#include <cuda_runtime.h>
#include <cuda_bf16.h>

// STSEarlyFusionConcat: out (1, 2C, D, H, W) fp32
//   out[c,d,h,w]    = (w>=d) ? x[c,h,w]   : 0    for c in [0,C)
//   out[C+c,d,h,w]  = (w>=d) ? y[c,h,w-d] : 0    for c in [0,C)
// B=1, C=32, H=96, W=192, D=64.
// R11 = R8 (best: 4 d/thread, coalesced float4, vectorized y-window loads)
// with stores switched .cs -> .wt (write-through): no dirty L2 lines, smooth
// continuous L2->DRAM drain instead of eviction bursts. Single-variable test;
// R8 remains the fallback optimum (43.5us = ~87% of HBM spec).

namespace {
constexpr int C   = 32;
constexpr int H   = 96;
constexpr int W   = 192;
constexpr int D   = 64;
constexpr int W4  = W / 4;                 // 48
constexpr int DQ  = D / 4;                 // 16
constexpr long long NTHREADS = (long long)(2 * C) * DQ * H * W4;  // 4,718,592
}

__global__ __launch_bounds__(256)
void stsef_kernel(const float* __restrict__ x,
                  const float* __restrict__ y,
                  float4* __restrict__ out)
{
    unsigned idx = blockIdx.x * blockDim.x + threadIdx.x;
    // idx = ((c2*DQ + dq)*H + h)*W4 + w4
    unsigned w4 = idx % W4;
    unsigned t  = idx / W4;
    unsigned h  = t % H;   t /= H;
    unsigned dq = t % DQ;  t /= DQ;
    unsigned c2 = t;                        // 0..63

    int w0 = (int)(w4 * 4);
    int d0 = (int)(dq * 4);

    size_t obase = (((size_t)(c2 * D + d0) * H) + h) * W4 + w4;  // float4 index
    const size_t dstr = (size_t)H * W4;                          // stride per d

    if (c2 < C) {
        // cost_x: one aligned vector load, 4 masked write-through stores
        const float4* xr = reinterpret_cast<const float4*>(x + ((c2 * H) + h) * W);
        float4 xv = __ldg(xr + w4);
#pragma unroll
        for (int k = 0; k < 4; k++) {
            int dd = d0 + k;
            float4 v;
            v.x = (w0 + 0 >= dd) ? xv.x : 0.0f;
            v.y = (w0 + 1 >= dd) ? xv.y : 0.0f;
            v.z = (w0 + 2 >= dd) ? xv.z : 0.0f;
            v.w = (w0 + 3 >= dd) ? xv.w : 0.0f;
            __stwt(out + obase + (size_t)k * dstr, v);
        }
    } else {
        // cost_y: window y[b-3..b+3], b = w0-d0 = 4*(w4-dq) (16B-aligned).
        // Two predicated vector loads; predicate == zero mask.
        const float4* yr4 = reinterpret_cast<const float4*>(
            y + (((c2 - C) * H) + h) * W);
        int q = (int)w4 - (int)dq;          // b/4
        float4 A  = make_float4(0.f, 0.f, 0.f, 0.f);
        float4 Bv = make_float4(0.f, 0.f, 0.f, 0.f);
        if (q >= 1) A  = __ldg(yr4 + (q - 1));   // y[b-4 .. b-1]
        if (q >= 0) Bv = __ldg(yr4 + q);         // y[b   .. b+3]
        // tv[i] = y[b-3+i] (0 if OOB):
        float tv[7];
        tv[0] = A.y;  tv[1] = A.z;  tv[2] = A.w;
        tv[3] = Bv.x; tv[4] = Bv.y; tv[5] = Bv.z; tv[6] = Bv.w;
#pragma unroll
        for (int k = 0; k < 4; k++) {
            // component j of store k = y[b + j - k] = tv[3 + j - k]
            float4 v;
            v.x = tv[3 - k];
            v.y = tv[4 - k];
            v.z = tv[5 - k];
            v.w = tv[6 - k];
            __stwt(out + obase + (size_t)k * dstr, v);
        }
    }
}

extern "C" void kernel_launch(void* const* d_in, const int* in_sizes, int n_in,
                              void* d_out, int out_size)
{
    const float* x = (const float*)d_in[0];
    const float* y = (const float*)d_in[1];
    float4* out = (float4*)d_out;

    const int threads = 256;
    const unsigned blocks = (unsigned)(NTHREADS / threads);  // 18,432
    stsef_kernel<<<blocks, threads>>>(x, y, out);
}

// round 12
// speedup vs baseline: 1.0941x; 1.0941x over previous
#include <cuda_runtime.h>
#include <cuda_bf16.h>

// STSEarlyFusionConcat: out (1, 2C, D, H, W) fp32
//   out[c,d,h,w]    = (w>=d) ? x[c,h,w]   : 0    for c in [0,C)
//   out[C+c,d,h,w]  = (w>=d) ? y[c,h,w-d] : 0    for c in [0,C)
// B=1, C=32, H=96, W=192, D=64.  HBM-write-bound: 302 MB out per launch.
//
// FINAL (== R8, the measured optimum: 43.5us wall = 6.94 TB/s ~ 87% of spec):
//  - each thread owns one (c2, h, w4) column x 4 consecutive d values
//    -> 4 independent coalesced STG.128 after all loads complete (.cs,
//       evict-first: keeps the 4.5 MB x/y inputs L2-resident)
//  - cost_x: 1 aligned LDG.128 serves 4 masked stores
//  - cost_y: b = w0-d0 = 4*(w4-dq) is 16B-aligned, so the 7-float window
//    y[b-3..b+3] is exactly 2 predicated LDG.128 (f4[q-1], f4[q]); the load
//    predicates (q>=1, q>=0) are precisely the w>=d zero-masks, and window
//    slicing into the 4 shifted stores is static register selection.
// Exhaustively tested alternatives (8d/thread, plane-per-block, TMA bulk
// store, .wb/.wt/hybrid policies, block interleaving) all measured worse.

namespace {
constexpr int C   = 32;
constexpr int H   = 96;
constexpr int W   = 192;
constexpr int D   = 64;
constexpr int W4  = W / 4;                 // 48
constexpr int DQ  = D / 4;                 // 16
constexpr long long NTHREADS = (long long)(2 * C) * DQ * H * W4;  // 4,718,592
}

__global__ __launch_bounds__(256)
void stsef_kernel(const float* __restrict__ x,
                  const float* __restrict__ y,
                  float4* __restrict__ out)
{
    unsigned idx = blockIdx.x * blockDim.x + threadIdx.x;
    // idx = ((c2*DQ + dq)*H + h)*W4 + w4
    unsigned w4 = idx % W4;
    unsigned t  = idx / W4;
    unsigned h  = t % H;   t /= H;
    unsigned dq = t % DQ;  t /= DQ;
    unsigned c2 = t;                        // 0..63

    int w0 = (int)(w4 * 4);
    int d0 = (int)(dq * 4);

    size_t obase = (((size_t)(c2 * D + d0) * H) + h) * W4 + w4;  // float4 index
    const size_t dstr = (size_t)H * W4;                          // stride per d

    if (c2 < C) {
        // cost_x: one aligned vector load, 4 masked streaming stores
        const float4* xr = reinterpret_cast<const float4*>(x + ((c2 * H) + h) * W);
        float4 xv = __ldg(xr + w4);
#pragma unroll
        for (int k = 0; k < 4; k++) {
            int dd = d0 + k;
            float4 v;
            v.x = (w0 + 0 >= dd) ? xv.x : 0.0f;
            v.y = (w0 + 1 >= dd) ? xv.y : 0.0f;
            v.z = (w0 + 2 >= dd) ? xv.z : 0.0f;
            v.w = (w0 + 3 >= dd) ? xv.w : 0.0f;
            __stcs(out + obase + (size_t)k * dstr, v);
        }
    } else {
        // cost_y: window y[b-3..b+3], b = w0-d0 = 4*(w4-dq) (16B-aligned).
        // Two predicated vector loads; predicate == zero mask.
        const float4* yr4 = reinterpret_cast<const float4*>(
            y + (((c2 - C) * H) + h) * W);
        int q = (int)w4 - (int)dq;          // b/4
        float4 A  = make_float4(0.f, 0.f, 0.f, 0.f);
        float4 Bv = make_float4(0.f, 0.f, 0.f, 0.f);
        if (q >= 1) A  = __ldg(yr4 + (q - 1));   // y[b-4 .. b-1]
        if (q >= 0) Bv = __ldg(yr4 + q);         // y[b   .. b+3]
        // tv[i] = y[b-3+i] (0 if OOB):
        float tv[7];
        tv[0] = A.y;  tv[1] = A.z;  tv[2] = A.w;
        tv[3] = Bv.x; tv[4] = Bv.y; tv[5] = Bv.z; tv[6] = Bv.w;
#pragma unroll
        for (int k = 0; k < 4; k++) {
            // component j of store k = y[b + j - k] = tv[3 + j - k]
            float4 v;
            v.x = tv[3 - k];
            v.y = tv[4 - k];
            v.z = tv[5 - k];
            v.w = tv[6 - k];
            __stcs(out + obase + (size_t)k * dstr, v);
        }
    }
}

extern "C" void kernel_launch(void* const* d_in, const int* in_sizes, int n_in,
                              void* d_out, int out_size)
{
    const float* x = (const float*)d_in[0];
    const float* y = (const float*)d_in[1];
    float4* out = (float4*)d_out;

    const int threads = 256;
    const unsigned blocks = (unsigned)(NTHREADS / threads);  // 18,432
    stsef_kernel<<<blocks, threads>>>(x, y, out);
}